// round 1
// baseline (speedup 1.0000x reference)
#include <cuda_runtime.h>
#include <math.h>

#define T 1024
#define H 1024
#define NH 8
#define NKV 4
#define HD 128
#define NE 32
#define MI 512
#define SI 1024

// ---------------- scratch (static device allocations; no cudaMalloc) ----------------
__device__ float g_h1[T*H];
__device__ float g_q[T*H];
__device__ float g_k[T*NKV*HD];
__device__ float g_v[T*NKV*HD];
__device__ float g_attn[T*H];
__device__ float g_ao[T*H];
__device__ float g_h2[T*H];
__device__ float g_x[T*H];
__device__ float g_logits[T*NE];
__device__ float g_topkw[T*4];
__device__ int   g_cnt[NE];
__device__ int   g_list[NE*T];
__device__ float g_eg[T*4*MI];
__device__ float g_eu[T*4*MI];
__device__ float g_ed[(size_t)T*4*H];
__device__ float g_sg[T*SI];
__device__ float g_su[T*SI];
__device__ float g_sh[T*H];

// ---------------- elementwise / norms ----------------
__global__ void rmsnorm_kernel(const float* __restrict__ x, const float* __restrict__ w,
                               float* __restrict__ out) {
    int t = blockIdx.x;
    const float* xr = x + (size_t)t * H;
    float s = 0.f;
    for (int i = threadIdx.x; i < H; i += blockDim.x) { float v = xr[i]; s += v * v; }
    __shared__ float red[32];
    for (int o = 16; o; o >>= 1) s += __shfl_xor_sync(0xffffffffu, s, o);
    if ((threadIdx.x & 31) == 0) red[threadIdx.x >> 5] = s;
    __syncthreads();
    if (threadIdx.x < 32) {
        float v = (threadIdx.x < (blockDim.x >> 5)) ? red[threadIdx.x] : 0.f;
        for (int o = 16; o; o >>= 1) v += __shfl_xor_sync(0xffffffffu, v, o);
        if (threadIdx.x == 0) red[0] = v;
    }
    __syncthreads();
    float inv = rsqrtf(red[0] * (1.f / H) + 1e-6f);
    for (int i = threadIdx.x; i < H; i += blockDim.x)
        out[(size_t)t * H + i] = xr[i] * inv * w[i];
}

__global__ void add_kernel(const float* __restrict__ a, const float* __restrict__ b,
                           float* __restrict__ o, int n) {
    int i = blockIdx.x * blockDim.x + threadIdx.x;
    if (i < n) o[i] = a[i] + b[i];
}

__global__ void silu_mul_kernel(const float* __restrict__ g, const float* __restrict__ u,
                                float* __restrict__ o, int n) {
    int i = blockIdx.x * blockDim.x + threadIdx.x;
    if (i < n) { float x = g[i]; o[i] = x / (1.f + __expf(-x)) * u[i]; }
}

__global__ void zero_cnt_kernel(int* cnt) {
    if (threadIdx.x < NE) cnt[threadIdx.x] = 0;
}

// ---------------- RoPE ----------------
__global__ void rope_kernel(float* __restrict__ q, float* __restrict__ k,
                            const int* __restrict__ pos) {
    int t = blockIdx.x;
    int i = threadIdx.x;          // 0..63 (half dim)
    int hh = threadIdx.y;         // 0..11 : 8 q-heads then 4 kv-heads
    float p = (float)pos[t];
    // inv_freq = 10000^(-i/64)
    float inv = exp2f(-(float)i * (13.287712379549449f / 64.f));
    float fr = p * inv;
    float sv, cv;
    sincosf(fr, &sv, &cv);
    float* base = (hh < 8) ? (q + (size_t)t * H + hh * HD)
                           : (k + (size_t)t * (NKV * HD) + (hh - 8) * HD);
    float x1 = base[i], x2 = base[i + 64];
    base[i]      = x1 * cv - x2 * sv;
    base[i + 64] = x2 * cv + x1 * sv;
}

// ---------------- generic tiled SGEMM: C[M,N] = A[M,K] @ op(B) ----------------
// BT=true : B is [N,K] row-major (NT gemm, weights stored (out,in))
// BT=false: B is [K,N] row-major (NN gemm)
template <bool BT>
__global__ void gemm_kernel(const float* __restrict__ A, const float* __restrict__ B,
                            float* __restrict__ C, int M, int N, int K) {
    __shared__ float As[16][68];
    __shared__ float Bs[16][68];
    const int tid = threadIdx.x;              // 256 threads
    const int m0 = blockIdx.y * 64, n0 = blockIdx.x * 64;
    const int tx = tid & 15, ty = tid >> 4;
    const int ar = tid >> 2, ac = (tid & 3) * 4;
    float acc[4][4] = {};
    for (int k0 = 0; k0 < K; k0 += 16) {
        {
            int gm = m0 + ar;
            float4 f = make_float4(0.f, 0.f, 0.f, 0.f);
            if (gm < M) f = *(const float4*)(A + (size_t)gm * K + k0 + ac);
            As[ac + 0][ar] = f.x; As[ac + 1][ar] = f.y;
            As[ac + 2][ar] = f.z; As[ac + 3][ar] = f.w;
        }
        if (BT) {
            int gn = n0 + ar;
            float4 f = make_float4(0.f, 0.f, 0.f, 0.f);
            if (gn < N) f = *(const float4*)(B + (size_t)gn * K + k0 + ac);
            Bs[ac + 0][ar] = f.x; Bs[ac + 1][ar] = f.y;
            Bs[ac + 2][ar] = f.z; Bs[ac + 3][ar] = f.w;
        } else {
            int br = tid >> 4, bc = (tid & 15) * 4;
            int gn = n0 + bc;
            float4 f = make_float4(0.f, 0.f, 0.f, 0.f);
            if (gn < N) f = *(const float4*)(B + (size_t)(k0 + br) * N + gn);
            *(float4*)&Bs[br][bc] = f;
        }
        __syncthreads();
#pragma unroll
        for (int kk = 0; kk < 16; kk++) {
            float a[4], b[4];
#pragma unroll
            for (int i = 0; i < 4; i++) a[i] = As[kk][ty * 4 + i];
#pragma unroll
            for (int j = 0; j < 4; j++) b[j] = Bs[kk][tx * 4 + j];
#pragma unroll
            for (int i = 0; i < 4; i++)
#pragma unroll
                for (int j = 0; j < 4; j++) acc[i][j] = fmaf(a[i], b[j], acc[i][j]);
        }
        __syncthreads();
    }
#pragma unroll
    for (int i = 0; i < 4; i++) {
        int gm = m0 + ty * 4 + i;
        if (gm >= M) continue;
#pragma unroll
        for (int j = 0; j < 4; j++) {
            int gn = n0 + tx * 4 + j;
            if (gn < N) C[(size_t)gm * N + gn] = acc[i][j];
        }
    }
}

// ---------------- expert gather GEMM: rows come from per-expert token lists ----------------
// list[e*T + i] = j = t*4 + slot. A-row = j >> shift (shift=2: gather x rows; shift=0: gather a rows).
// C-row = j. W is [E][K][N] row-major, NN.
__global__ void expert_gemm_kernel(const float* __restrict__ A, const float* __restrict__ W,
                                   float* __restrict__ C, const int* __restrict__ cnt,
                                   const int* __restrict__ list, int K, int N, int shift) {
    const int e = blockIdx.z;
    const int me = cnt[e];
    const int m0 = blockIdx.y * 64;
    if (m0 >= me) return;
    const int n0 = blockIdx.x * 64;
    __shared__ int rows[64];
    __shared__ float As[16][68];
    __shared__ float Bs[16][68];
    const int tid = threadIdx.x;
    if (tid < 64) rows[tid] = (m0 + tid < me) ? list[e * T + m0 + tid] : -1;
    __syncthreads();
    const float* Wb = W + (size_t)e * K * N;
    const int tx = tid & 15, ty = tid >> 4;
    const int ar = tid >> 2, ac = (tid & 3) * 4;
    const int br = tid >> 4, bc = (tid & 15) * 4;
    float acc[4][4] = {};
    for (int k0 = 0; k0 < K; k0 += 16) {
        {
            int j = rows[ar];
            int arow = (j < 0) ? 0 : (j >> shift);
            float4 f = *(const float4*)(A + (size_t)arow * K + k0 + ac);
            As[ac + 0][ar] = f.x; As[ac + 1][ar] = f.y;
            As[ac + 2][ar] = f.z; As[ac + 3][ar] = f.w;
        }
        {
            float4 f = *(const float4*)(Wb + (size_t)(k0 + br) * N + n0 + bc);
            *(float4*)&Bs[br][bc] = f;
        }
        __syncthreads();
#pragma unroll
        for (int kk = 0; kk < 16; kk++) {
            float a[4], b[4];
#pragma unroll
            for (int i = 0; i < 4; i++) a[i] = As[kk][ty * 4 + i];
#pragma unroll
            for (int j = 0; j < 4; j++) b[j] = Bs[kk][tx * 4 + j];
#pragma unroll
            for (int i = 0; i < 4; i++)
#pragma unroll
                for (int j = 0; j < 4; j++) acc[i][j] = fmaf(a[i], b[j], acc[i][j]);
        }
        __syncthreads();
    }
#pragma unroll
    for (int i = 0; i < 4; i++) {
        int j = rows[ty * 4 + i];
        if (j < 0) continue;
#pragma unroll
        for (int jj = 0; jj < 4; jj++)
            C[(size_t)j * N + n0 + tx * 4 + jj] = acc[i][jj];
    }
}

// ---------------- causal flash attention (fp32, online softmax) ----------------
// grid: (NH, T/32). block: 256 = 8 warps; each warp owns 4 queries, dims split 4/lane.
__global__ void attn_kernel(const float* __restrict__ q, const float* __restrict__ k,
                            const float* __restrict__ v, float* __restrict__ out) {
    const int h = blockIdx.x;
    const int qt = gridDim.y - 1 - blockIdx.y;   // heavy tiles scheduled first
    const int kvh = h >> 1;                       // rep = NH/NKV = 2
    const int warp = threadIdx.x >> 5, lane = threadIdx.x & 31;
    __shared__ float Ks[32][HD];
    __shared__ float Vs[32][HD];
    const int q0 = qt * 32 + warp * 4;
    float qr[4][4];
#pragma unroll
    for (int i = 0; i < 4; i++) {
        float4 f = *(const float4*)(q + (size_t)(q0 + i) * H + h * HD + lane * 4);
        qr[i][0] = f.x; qr[i][1] = f.y; qr[i][2] = f.z; qr[i][3] = f.w;
    }
    float acc[4][4] = {};
    float mx[4] = {-1e30f, -1e30f, -1e30f, -1e30f};
    float ls[4] = {0.f, 0.f, 0.f, 0.f};
    const float scale = 0.088388347648318447f;    // 1/sqrt(128)
    for (int kt = 0; kt <= qt; kt++) {
        __syncthreads();
        for (int r = warp; r < 32; r += 8) {
            int kr = kt * 32 + r;
            *(float4*)&Ks[r][lane * 4] =
                *(const float4*)(k + (size_t)kr * (NKV * HD) + kvh * HD + lane * 4);
            *(float4*)&Vs[r][lane * 4] =
                *(const float4*)(v + (size_t)kr * (NKV * HD) + kvh * HD + lane * 4);
        }
        __syncthreads();
        const bool diag = (kt == qt);
        for (int j = 0; j < 32; j++) {
            const int kg = kt * 32 + j;
            float kv0 = Ks[j][lane * 4 + 0], kv1 = Ks[j][lane * 4 + 1];
            float kv2 = Ks[j][lane * 4 + 2], kv3 = Ks[j][lane * 4 + 3];
            float4 vv = *(const float4*)&Vs[j][lane * 4];
#pragma unroll
            for (int i = 0; i < 4; i++) {
                if (diag && kg > q0 + i) continue;   // causal mask (uniform across lanes)
                float p = qr[i][0] * kv0 + qr[i][1] * kv1 + qr[i][2] * kv2 + qr[i][3] * kv3;
                p += __shfl_xor_sync(0xffffffffu, p, 16);
                p += __shfl_xor_sync(0xffffffffu, p, 8);
                p += __shfl_xor_sync(0xffffffffu, p, 4);
                p += __shfl_xor_sync(0xffffffffu, p, 2);
                p += __shfl_xor_sync(0xffffffffu, p, 1);
                float s = p * scale;
                if (s > mx[i]) {
                    float c = __expf(mx[i] - s);
                    ls[i] = ls[i] * c + 1.f;
                    acc[i][0] = acc[i][0] * c + vv.x;
                    acc[i][1] = acc[i][1] * c + vv.y;
                    acc[i][2] = acc[i][2] * c + vv.z;
                    acc[i][3] = acc[i][3] * c + vv.w;
                    mx[i] = s;
                } else {
                    float e = __expf(s - mx[i]);
                    ls[i] += e;
                    acc[i][0] += e * vv.x;
                    acc[i][1] += e * vv.y;
                    acc[i][2] += e * vv.z;
                    acc[i][3] += e * vv.w;
                }
            }
        }
    }
#pragma unroll
    for (int i = 0; i < 4; i++) {
        float inv = 1.f / ls[i];
        float4 o;
        o.x = acc[i][0] * inv; o.y = acc[i][1] * inv;
        o.z = acc[i][2] * inv; o.w = acc[i][3] * inv;
        *(float4*)(out + (size_t)(q0 + i) * H + h * HD + lane * 4) = o;
    }
}

// ---------------- router (one thread per token; E=32 is tiny) ----------------
__global__ void router_kernel(const float* __restrict__ logits, const float* __restrict__ bias,
                              float* __restrict__ topkw, int* __restrict__ cnt,
                              int* __restrict__ list) {
    int t = blockIdx.x * blockDim.x + threadIdx.x;
    if (t >= T) return;
    float sc[NE], sfc[NE];
#pragma unroll
    for (int e = 0; e < NE; e++) {
        float l = logits[t * NE + e];
        float s = 1.f / (1.f + __expf(-l));
        sc[e] = s; sfc[e] = s + bias[e];
    }
    // group scores: sum of top-2 within each group of 4
    float gs[8];
#pragma unroll
    for (int g = 0; g < 8; g++) {
        float v0 = sfc[g*4+0], v1 = sfc[g*4+1], v2 = sfc[g*4+2], v3 = sfc[g*4+3];
        float sum = v0 + v1 + v2 + v3;
        float v[4] = {v0, v1, v2, v3};
        int mi = 0;
        for (int i = 1; i < 4; i++) if (v[i] < v[mi]) mi = i;
        float m2 = 1e30f;
        for (int i = 0; i < 4; i++) if (i != mi && v[i] < m2) m2 = v[i];
        gs[g] = sum - v[mi] - m2;
    }
    // top-4 groups (ties: lowest index, matching jax top_k)
    bool gsel[8] = {};
    for (int r = 0; r < 4; r++) {
        float best = -1e30f; int bi = 0;
        for (int g = 0; g < 8; g++) if (!gsel[g] && gs[g] > best) { best = gs[g]; bi = g; }
        gsel[bi] = true;
    }
    float masked[NE];
#pragma unroll
    for (int e = 0; e < NE; e++) masked[e] = gsel[e >> 2] ? sfc[e] : 0.f;
    int idxs[4]; float ws[4]; float wsum = 0.f;
    for (int r = 0; r < 4; r++) {
        float best = -1e30f; int bi = 0;
        for (int e = 0; e < NE; e++) if (masked[e] > best) { best = masked[e]; bi = e; }
        masked[bi] = -1e30f;
        idxs[r] = bi; ws[r] = sc[bi]; wsum += ws[r];
    }
    float inv = 2.5f / (wsum + 1e-20f);   // RSF applied here
    for (int r = 0; r < 4; r++) {
        topkw[t * 4 + r] = ws[r] * inv;
        int e = idxs[r];
        int pos = atomicAdd(&cnt[e], 1);          // int atomic: list order irrelevant to floats
        list[e * T + pos] = t * 4 + r;
    }
}

// ---------------- final combine ----------------
__global__ void final_kernel(const float* __restrict__ h2, const float* __restrict__ sh,
                             const float* __restrict__ ed, const float* __restrict__ tw,
                             float* __restrict__ out) {
    int idx = blockIdx.x * blockDim.x + threadIdx.x;
    if (idx >= T * H) return;
    int t = idx >> 10;
    int hh = idx & 1023;
    float r = h2[idx] + sh[idx];
#pragma unroll
    for (int kk = 0; kk < 4; kk++)
        r += tw[t * 4 + kk] * ed[(size_t)(t * 4 + kk) * H + hh];
    out[idx] = r;
}

// ---------------- host orchestration ----------------
extern "C" void kernel_launch(void* const* d_in, const int* in_sizes, int n_in,
                              void* d_out, int out_size) {
    (void)in_sizes; (void)n_in; (void)out_size;
    const float* hidden   = (const float*)d_in[0];
    const int*   pos      = (const int*)d_in[1];
    const float* ln1_w    = (const float*)d_in[2];
    const float* ln2_w    = (const float*)d_in[3];
    const float* q_w      = (const float*)d_in[4];
    const float* k_w      = (const float*)d_in[5];
    const float* v_w      = (const float*)d_in[6];
    const float* o_w      = (const float*)d_in[7];
    const float* router_w = (const float*)d_in[8];
    const float* r_bias   = (const float*)d_in[9];
    const float* eg_w     = (const float*)d_in[10];
    const float* eu_w     = (const float*)d_in[11];
    const float* ed_w     = (const float*)d_in[12];
    const float* sg_w     = (const float*)d_in[13];
    const float* su_w     = (const float*)d_in[14];
    const float* sd_w     = (const float*)d_in[15];
    float* out = (float*)d_out;

    float *h1, *qb, *kb, *vb, *attn, *ao, *h2, *xb, *logits, *topkw, *eg, *eu, *ed, *sg, *su, *sh;
    int *cnt, *list;
    cudaGetSymbolAddress((void**)&h1, g_h1);
    cudaGetSymbolAddress((void**)&qb, g_q);
    cudaGetSymbolAddress((void**)&kb, g_k);
    cudaGetSymbolAddress((void**)&vb, g_v);
    cudaGetSymbolAddress((void**)&attn, g_attn);
    cudaGetSymbolAddress((void**)&ao, g_ao);
    cudaGetSymbolAddress((void**)&h2, g_h2);
    cudaGetSymbolAddress((void**)&xb, g_x);
    cudaGetSymbolAddress((void**)&logits, g_logits);
    cudaGetSymbolAddress((void**)&topkw, g_topkw);
    cudaGetSymbolAddress((void**)&cnt, g_cnt);
    cudaGetSymbolAddress((void**)&list, g_list);
    cudaGetSymbolAddress((void**)&eg, g_eg);
    cudaGetSymbolAddress((void**)&eu, g_eu);
    cudaGetSymbolAddress((void**)&ed, g_ed);
    cudaGetSymbolAddress((void**)&sg, g_sg);
    cudaGetSymbolAddress((void**)&su, g_su);
    cudaGetSymbolAddress((void**)&sh, g_sh);

    zero_cnt_kernel<<<1, 32>>>(cnt);

    // ----- attention branch -----
    rmsnorm_kernel<<<T, 256>>>(hidden, ln1_w, h1);
    gemm_kernel<true><<<dim3(H / 64, T / 64), 256>>>(h1, q_w, qb, T, H, H);
    gemm_kernel<true><<<dim3((NKV * HD) / 64, T / 64), 256>>>(h1, k_w, kb, T, NKV * HD, H);
    gemm_kernel<true><<<dim3((NKV * HD) / 64, T / 64), 256>>>(h1, v_w, vb, T, NKV * HD, H);
    rope_kernel<<<T, dim3(64, 12)>>>(qb, kb, pos);
    attn_kernel<<<dim3(NH, T / 32), 256>>>(qb, kb, vb, attn);
    gemm_kernel<true><<<dim3(H / 64, T / 64), 256>>>(attn, o_w, ao, T, H, H);
    add_kernel<<<(T * H + 255) / 256, 256>>>(hidden, ao, h2, T * H);

    // ----- MoE branch -----
    rmsnorm_kernel<<<T, 256>>>(h2, ln2_w, xb);
    gemm_kernel<true><<<dim3(1, T / 64), 256>>>(xb, router_w, logits, T, NE, H);
    router_kernel<<<(T + 255) / 256, 256>>>(logits, r_bias, topkw, cnt, list);

    // routed experts: grouped gather-GEMMs (top-4 sparse, NOT dense over E)
    expert_gemm_kernel<<<dim3(MI / 64, T / 64, NE), 256>>>(xb, eg_w, eg, cnt, list, H, MI, 2);
    expert_gemm_kernel<<<dim3(MI / 64, T / 64, NE), 256>>>(xb, eu_w, eu, cnt, list, H, MI, 2);
    silu_mul_kernel<<<(T * 4 * MI + 255) / 256, 256>>>(eg, eu, eg, T * 4 * MI);
    expert_gemm_kernel<<<dim3(H / 64, T / 64, NE), 256>>>(eg, ed_w, ed, cnt, list, MI, H, 0);

    // shared expert
    gemm_kernel<false><<<dim3(SI / 64, T / 64), 256>>>(xb, sg_w, sg, T, SI, H);
    gemm_kernel<false><<<dim3(SI / 64, T / 64), 256>>>(xb, su_w, su, T, SI, H);
    silu_mul_kernel<<<(T * SI + 255) / 256, 256>>>(sg, su, sg, T * SI);
    gemm_kernel<false><<<dim3(H / 64, T / 64), 256>>>(sg, sd_w, sh, T, H, SI);

    final_kernel<<<(T * H + 255) / 256, 256>>>(h2, sh, ed, topkw, out);
}